// round 9
// baseline (speedup 1.0000x reference)
#include <cuda_runtime.h>
#include <cuda_fp16.h>
#include <cuda_fp8.h>
#include <math.h>
#include <stdint.h>

#define BATCH 4
#define SEQ   4096
#define DIM   512
#define MTOT  (BATCH * SEQ)
#define NTILE (SEQ / 128)
#define NEG_INF __int_as_float(0xff800000)

// ---------------- scratch (static device globals; no allocation) ------------
__device__ __half  g_Xh[(size_t)MTOT * DIM];
__device__ uint8_t g_X4[(size_t)MTOT * DIM];   // e4m3((X - Xh) * 2^6)
__device__ uint8_t g_X5[(size_t)MTOT * DIM];   // e5m2(X * 2^-12)
__device__ __half  g_Wh[3][DIM * DIM];
__device__ uint8_t g_W5[3][DIM * DIM];         // e5m2(W * 2^-6)
__device__ uint8_t g_W4[3][DIM * DIM];         // e4m3((W - Wh) * 2^12)
__device__ __half  g_Qh[(size_t)MTOT * DIM];
__device__ uint8_t g_Q4[(size_t)MTOT * DIM];   // e4m3((Q - Qh) * 2^12)
__device__ uint8_t g_Q5[(size_t)MTOT * DIM];   // e5m2(Q * 2^-12)
__device__ __half  g_Kh[(size_t)MTOT * DIM];
__device__ uint8_t g_K4[(size_t)MTOT * DIM];
__device__ uint8_t g_K5[(size_t)MTOT * DIM];
__device__ __half  g_Vth[(size_t)DIM * MTOT];  // V^T hi plane only
__device__ float   g_S [(size_t)BATCH * SEQ * SEQ];
__device__ __half  g_Ph[(size_t)BATCH * SEQ * SEQ];
__device__ float   g_cm[(size_t)NTILE * BATCH * SEQ];
__device__ float   g_cz[(size_t)NTILE * BATCH * SEQ];
__device__ float   g_m [(size_t)BATCH * SEQ];
__device__ float   g_rz[(size_t)BATCH * SEQ];

// ---------------- fast exp on the FMA pipe -----------------------------------
__device__ __forceinline__ float fast_exp(float x) {
    x = fmaxf(x, -80.0f);
    const float y  = x * 1.4426950408889634f;
    const float t  = y + 12582912.0f;
    const int   ni = __float_as_int(t) - 0x4B400000;
    const float f  = y - (t - 12582912.0f);
    float p = 1.3333558146e-3f;
    p = fmaf(p, f, 9.6181291076e-3f);
    p = fmaf(p, f, 5.5504108664e-2f);
    p = fmaf(p, f, 2.4022650696e-1f);
    p = fmaf(p, f, 6.9314718056e-1f);
    p = fmaf(p, f, 1.0f);
    return __int_as_float(__float_as_int(p) + (ni << 23));
}

// ---------------- fp8 pack helpers ------------------------------------------
__device__ __forceinline__ uint16_t f2_e4m3(float a, float b) {
    return __nv_cvt_float2_to_fp8x2(make_float2(a, b), __NV_SATFINITE, __NV_E4M3);
}
__device__ __forceinline__ uint16_t f2_e5m2(float a, float b) {
    return __nv_cvt_float2_to_fp8x2(make_float2(a, b), __NV_SATFINITE, __NV_E5M2);
}

// ============================ PTX helpers ===================================
__device__ __forceinline__ uint32_t smem_u32(const void* p) {
    uint32_t a;
    asm("{ .reg .u64 t; cvta.to.shared.u64 t, %1; cvt.u32.u64 %0, t; }"
        : "=r"(a) : "l"(p));
    return a;
}
template<int N> __device__ __forceinline__ void cp_wait() {
    asm volatile("cp.async.wait_group %0;" :: "n"(N) : "memory");
}
__device__ __forceinline__ void cp_commit() {
    asm volatile("cp.async.commit_group;" ::: "memory");
}
__device__ __forceinline__ void cp16(uint32_t dst, const void* src) {
    asm volatile("cp.async.cg.shared.global [%0], [%1], 16;"
                 :: "r"(dst), "l"(src) : "memory");
}
__device__ __forceinline__ void ldsm4(uint32_t* r, uint32_t a) {
    asm volatile("ldmatrix.sync.aligned.m8n8.x4.shared.b16 {%0,%1,%2,%3}, [%4];"
                 : "=r"(r[0]), "=r"(r[1]), "=r"(r[2]), "=r"(r[3]) : "r"(a));
}
__device__ __forceinline__ void mma16816(float* d, const uint32_t* a,
                                         uint32_t b0, uint32_t b1) {
    asm volatile("mma.sync.aligned.m16n8k16.row.col.f32.f16.f16.f32 "
                 "{%0,%1,%2,%3},{%4,%5,%6,%7},{%8,%9},{%0,%1,%2,%3};"
                 : "+f"(d[0]), "+f"(d[1]), "+f"(d[2]), "+f"(d[3])
                 : "r"(a[0]), "r"(a[1]), "r"(a[2]), "r"(a[3]), "r"(b0), "r"(b1));
}
// fp8 k32 MMAs: A = e4m3, B = e5m2 (c1) and A = e5m2, B = e4m3 (c2)
__device__ __forceinline__ void mma_45(float* d, const uint32_t* a,
                                       uint32_t b0, uint32_t b1) {
    asm volatile("mma.sync.aligned.m16n8k32.row.col.f32.e4m3.e5m2.f32 "
                 "{%0,%1,%2,%3},{%4,%5,%6,%7},{%8,%9},{%0,%1,%2,%3};"
                 : "+f"(d[0]), "+f"(d[1]), "+f"(d[2]), "+f"(d[3])
                 : "r"(a[0]), "r"(a[1]), "r"(a[2]), "r"(a[3]), "r"(b0), "r"(b1));
}
__device__ __forceinline__ void mma_54(float* d, const uint32_t* a,
                                       uint32_t b0, uint32_t b1) {
    asm volatile("mma.sync.aligned.m16n8k32.row.col.f32.e5m2.e4m3.f32 "
                 "{%0,%1,%2,%3},{%4,%5,%6,%7},{%8,%9},{%0,%1,%2,%3};"
                 : "+f"(d[0]), "+f"(d[1]), "+f"(d[2]), "+f"(d[3])
                 : "r"(a[0]), "r"(a[1]), "r"(a[2]), "r"(a[3]), "r"(b0), "r"(b1));
}

// ============================ GEMM ==========================================
// C[m,n] = sum_k A[m,k]*B[n,k]
// FP8C=1: hi*hi in fp16 (2x k16) + 2 fp8 k32 corrections into same acc
// FP8C=0: hi*hi only (PV path)
// EPI 0: fp32 C[m][n], no bias
// EPI 1: fp16 hi Ch + e4m3 resid C4 (x2^12) + e5m2 hi C5 (x2^-12), +bias
// EPI 2: fp16 hi plane Ch[n][m] (+bias)  -- transposed (for V^T)
// EPI 3: fp32 C[m][n] + per-tile column softmax stats -> g_cm/g_cz
#define TCT 256

template<int EPI, int FP8C>
__global__ void __launch_bounds__(TCT, 2)
gemm_f8(const __half* __restrict__ Ah, const uint8_t* __restrict__ A4,
        const uint8_t* __restrict__ A5,
        const __half* __restrict__ Bh, const uint8_t* __restrict__ B5,
        const uint8_t* __restrict__ B4,
        const float* __restrict__ bias,
        float* __restrict__ C, __half* __restrict__ Ch,
        uint8_t* __restrict__ C4, uint8_t* __restrict__ C5,
        int K, int lda, int ldb, int ldc,
        long sA, long sB, long sC)
{
    constexpr int OFF_BH = 8192;
    constexpr int OFF_A4 = 16384;
    constexpr int OFF_B5 = 20480;
    constexpr int OFF_A5 = 24576;
    constexpr int OFF_B4 = 28672;
    constexpr int STG    = FP8C ? 32768 : 16384;

    extern __shared__ __align__(128) char smem[];
    const uint32_t sb = smem_u32(smem);

    const int tid = threadIdx.x;
    const int lid = tid & 31;
    const int wid = tid >> 5;
    const int wm  = wid >> 2;
    const int wn  = wid & 3;

    const long z = blockIdx.z;
    Ah += z * sA; Bh += z * sB;
    if (FP8C) { A4 += z * sA; A5 += z * sA; B5 += z * sB; B4 += z * sB; }
    if (EPI == 0 || EPI == 3) C += z * sC;
    else { Ch += z * sC; if (EPI == 1) { C4 += z * sC; C5 += z * sC; } }

    const int m0 = blockIdx.y * 128;
    const int n0 = blockIdx.x * 128;

    const int nstage = K / 32;

    auto issue = [&](int s) {
        const uint32_t base = sb + (s & 1) * STG;
        const int k0 = s * 32;
#pragma unroll
        for (int i = 0; i < 2; i++) {
            const int chunk = i * 256 + tid;
            const int r = chunk >> 2;
            const int c = chunk & 3;
            const uint32_t doff = r * 64 + ((c ^ ((r + (r >> 2)) & 3)) * 16);
            cp16(base + doff,          Ah + (size_t)(m0 + r) * lda + k0 + c * 8);
            cp16(base + OFF_BH + doff, Bh + (size_t)(n0 + r) * ldb + k0 + c * 8);
        }
        if (FP8C) {
            const int r8 = tid >> 1;
            const int c8 = tid & 1;
            const uint32_t d8 = r8 * 32 + ((c8 ^ ((r8 + (r8 >> 2)) & 1)) * 16);
            cp16(base + OFF_A4 + d8, A4 + (size_t)(m0 + r8) * lda + k0 + c8 * 16);
            cp16(base + OFF_B5 + d8, B5 + (size_t)(n0 + r8) * ldb + k0 + c8 * 16);
            cp16(base + OFF_A5 + d8, A5 + (size_t)(m0 + r8) * lda + k0 + c8 * 16);
            cp16(base + OFF_B4 + d8, B4 + (size_t)(n0 + r8) * ldb + k0 + c8 * 16);
        }
        cp_commit();
    };

    float acc[4][4][4];
#pragma unroll
    for (int a = 0; a < 4; a++)
#pragma unroll
        for (int b = 0; b < 4; b++)
#pragma unroll
            for (int c = 0; c < 4; c++) acc[a][b][c] = 0.f;

    const int sub   = lid >> 3;
    const int lane7 = lid & 7;
    const int rA = wm * 64 + (sub & 1) * 8 + lane7;
    const int rB = wn * 32 + (sub & 1) * 8 + lane7;
    const int cs = sub >> 1;
    const int swA = (rA + (rA >> 2)) & 3;
    const int swB = (rB + (rB >> 2)) & 3;
    const uint32_t a8off = ((cs ^ ((rA + (rA >> 2)) & 1)) * 16);
    const uint32_t b8off = ((cs ^ ((rB + (rB >> 2)) & 1)) * 16);

    issue(0);
    issue(1);

    for (int s = 0; s < nstage; s++) {
        if (s + 1 < nstage) cp_wait<1>(); else cp_wait<0>();
        __syncthreads();

        const uint32_t stg = sb + (s & 1) * STG;

        // ---- hi*hi in fp16 (2 x k16) ----
#pragma unroll
        for (int kt = 0; kt < 2; kt++) {
            const int ch = 2 * kt + cs;
            const uint32_t aoff = ((ch ^ swA) * 16);
            const uint32_t boff = ((ch ^ swB) * 16);

            uint32_t aH[4][4], bH[2][4];
#pragma unroll
            for (int mf = 0; mf < 4; mf++)
                ldsm4(aH[mf], stg + (rA + mf * 16) * 64 + aoff);
#pragma unroll
            for (int bg = 0; bg < 2; bg++)
                ldsm4(bH[bg], stg + OFF_BH + (rB + bg * 16) * 64 + boff);

#pragma unroll
            for (int mf = 0; mf < 4; mf++)
#pragma unroll
                for (int nf = 0; nf < 4; nf++)
                    mma16816(acc[mf][nf], aH[mf],
                             bH[nf >> 1][nf & 1], bH[nf >> 1][(nf & 1) + 2]);
        }

        // ---- fp8 corrections (full k32 each) ----
        if (FP8C) {
            uint32_t a8[4][4], b8[2][4];
            // c1: e4m3 A-resid x e5m2 B-hi
#pragma unroll
            for (int mf = 0; mf < 4; mf++)
                ldsm4(a8[mf], stg + OFF_A4 + (rA + mf * 16) * 32 + a8off);
#pragma unroll
            for (int bg = 0; bg < 2; bg++)
                ldsm4(b8[bg], stg + OFF_B5 + (rB + bg * 16) * 32 + b8off);
#pragma unroll
            for (int mf = 0; mf < 4; mf++)
#pragma unroll
                for (int nf = 0; nf < 4; nf++)
                    mma_45(acc[mf][nf], a8[mf],
                           b8[nf >> 1][nf & 1], b8[nf >> 1][(nf & 1) + 2]);
            // c2: e5m2 A-hi x e4m3 B-resid
#pragma unroll
            for (int mf = 0; mf < 4; mf++)
                ldsm4(a8[mf], stg + OFF_A5 + (rA + mf * 16) * 32 + a8off);
#pragma unroll
            for (int bg = 0; bg < 2; bg++)
                ldsm4(b8[bg], stg + OFF_B4 + (rB + bg * 16) * 32 + b8off);
#pragma unroll
            for (int mf = 0; mf < 4; mf++)
#pragma unroll
                for (int nf = 0; nf < 4; nf++)
                    mma_54(acc[mf][nf], a8[mf],
                           b8[nf >> 1][nf & 1], b8[nf >> 1][(nf & 1) + 2]);
        }

        if (s + 2 < nstage) {
            __syncthreads();
            issue(s + 2);
        }
    }

    // -------------------------- epilogue ------------------------------------
#pragma unroll
    for (int mf = 0; mf < 4; mf++) {
#pragma unroll
        for (int nf = 0; nf < 4; nf++) {
            const int m = m0 + wm * 64 + mf * 16 + (lid >> 2);
            const int n = n0 + wn * 32 + nf * 8 + (lid & 3) * 2;
            float v0 = acc[mf][nf][0], v1 = acc[mf][nf][1];
            float v2 = acc[mf][nf][2], v3 = acc[mf][nf][3];
            if (EPI == 1 || EPI == 2) {
                const float b0 = bias[n], b1 = bias[n + 1];
                v0 += b0; v1 += b1; v2 += b0; v3 += b1;
            }
            if (EPI == 0 || EPI == 3) {
                *(float2*)(C + (size_t)m * ldc + n)       = make_float2(v0, v1);
                *(float2*)(C + (size_t)(m + 8) * ldc + n) = make_float2(v2, v3);
            } else {
                __half h0 = __float2half_rn(v0), h1 = __float2half_rn(v1);
                __half h2 = __float2half_rn(v2), h3 = __float2half_rn(v3);
                if (EPI == 1) {
                    const float f0 = __half2float(h0), f1 = __half2float(h1);
                    const float f2 = __half2float(h2), f3 = __half2float(h3);
                    *(__half2*)(Ch + (size_t)m * ldc + n)       = __halves2half2(h0, h1);
                    *(__half2*)(Ch + (size_t)(m + 8) * ldc + n) = __halves2half2(h2, h3);
                    *(uint16_t*)(C4 + (size_t)m * ldc + n) =
                        f2_e4m3((v0 - f0) * 4096.f, (v1 - f1) * 4096.f);
                    *(uint16_t*)(C4 + (size_t)(m + 8) * ldc + n) =
                        f2_e4m3((v2 - f2) * 4096.f, (v3 - f3) * 4096.f);
                    *(uint16_t*)(C5 + (size_t)m * ldc + n) =
                        f2_e5m2(v0 * 2.44140625e-4f, v1 * 2.44140625e-4f);
                    *(uint16_t*)(C5 + (size_t)(m + 8) * ldc + n) =
                        f2_e5m2(v2 * 2.44140625e-4f, v3 * 2.44140625e-4f);
                } else {
                    Ch[(size_t)n * ldc + m]           = h0;
                    Ch[(size_t)(n + 1) * ldc + m]     = h1;
                    Ch[(size_t)n * ldc + m + 8]       = h2;
                    Ch[(size_t)(n + 1) * ldc + m + 8] = h3;
                }
            }
        }
    }

    // ---------------- fused column softmax partials (EPI 3) ----------------
    if (EPI == 3) {
        __syncthreads();
        float* st = (float*)smem;

        float cm[8], cz[8];
#pragma unroll
        for (int nf = 0; nf < 4; nf++) {
#pragma unroll
            for (int e = 0; e < 2; e++) {
                float mx = NEG_INF;
#pragma unroll
                for (int mf = 0; mf < 4; mf++) {
                    mx = fmaxf(mx, acc[mf][nf][e]);
                    mx = fmaxf(mx, acc[mf][nf][e + 2]);
                }
                float zz = 0.f;
#pragma unroll
                for (int mf = 0; mf < 4; mf++)
                    zz += fast_exp(acc[mf][nf][e] - mx) + fast_exp(acc[mf][nf][e + 2] - mx);
                cm[nf * 2 + e] = mx;
                cz[nf * 2 + e] = zz;
            }
        }
#pragma unroll
        for (int off = 4; off < 32; off <<= 1) {
#pragma unroll
            for (int c = 0; c < 8; c++) {
                const float om = __shfl_xor_sync(0xffffffff, cm[c], off);
                const float oz = __shfl_xor_sync(0xffffffff, cz[c], off);
                const float mn = fmaxf(cm[c], om);
                cz[c] = cz[c] * fast_exp(cm[c] - mn) + oz * fast_exp(om - mn);
                cm[c] = mn;
            }
        }
        if ((lid >> 2) == 0) {
#pragma unroll
            for (int nf = 0; nf < 4; nf++)
#pragma unroll
                for (int e = 0; e < 2; e++) {
                    const int col = wn * 32 + nf * 8 + (lid & 3) * 2 + e;
                    st[(wm * 128 + col) * 2 + 0] = cm[nf * 2 + e];
                    st[(wm * 128 + col) * 2 + 1] = cz[nf * 2 + e];
                }
        }
        __syncthreads();
        if (tid < 128) {
            const float m0v = st[tid * 2],         z0v = st[tid * 2 + 1];
            const float m1v = st[(128 + tid) * 2], z1v = st[(128 + tid) * 2 + 1];
            const float mn = fmaxf(m0v, m1v);
            const float zz = z0v * fast_exp(m0v - mn) + z1v * fast_exp(m1v - mn);
            const size_t o = ((size_t)blockIdx.y * BATCH + blockIdx.z) * SEQ + n0 + tid;
            g_cm[o] = mn;
            g_cz[o] = zz;
        }
    }
}

// ---------------------------------------------------------------------------
// X -> Xh fp16, X4 = e4m3((X-Xh)*2^6), X5 = e5m2(X*2^-12)
__global__ void __launch_bounds__(256)
split_x(const float* __restrict__ src, __half* __restrict__ h,
        uint8_t* __restrict__ p4, uint8_t* __restrict__ p5, int n4)
{
    const int i = blockIdx.x * 256 + threadIdx.x;
    if (i >= n4) return;
    const float4 v = ((const float4*)src)[i];
    float vv[4] = {v.x, v.y, v.z, v.w};
    __half hh[4]; float hf[4];
#pragma unroll
    for (int e = 0; e < 4; e++) { hh[e] = __float2half_rn(vv[e]); hf[e] = __half2float(hh[e]); }
    ((__half2*)h)[i * 2]     = __halves2half2(hh[0], hh[1]);
    ((__half2*)h)[i * 2 + 1] = __halves2half2(hh[2], hh[3]);
    ((uint16_t*)p4)[i * 2]     = f2_e4m3((vv[0] - hf[0]) * 64.f, (vv[1] - hf[1]) * 64.f);
    ((uint16_t*)p4)[i * 2 + 1] = f2_e4m3((vv[2] - hf[2]) * 64.f, (vv[3] - hf[3]) * 64.f);
    ((uint16_t*)p5)[i * 2]     = f2_e5m2(vv[0] * 2.44140625e-4f, vv[1] * 2.44140625e-4f);
    ((uint16_t*)p5)[i * 2 + 1] = f2_e5m2(vv[2] * 2.44140625e-4f, vv[3] * 2.44140625e-4f);
}

// W -> Wh fp16, W5 = e5m2(W*2^-6), W4 = e4m3((W-Wh)*2^12)
__global__ void __launch_bounds__(256)
split_w(const float* __restrict__ src, __half* __restrict__ h,
        uint8_t* __restrict__ p5, uint8_t* __restrict__ p4, int n4)
{
    const int i = blockIdx.x * 256 + threadIdx.x;
    if (i >= n4) return;
    const float4 v = ((const float4*)src)[i];
    float vv[4] = {v.x, v.y, v.z, v.w};
    __half hh[4]; float hf[4];
#pragma unroll
    for (int e = 0; e < 4; e++) { hh[e] = __float2half_rn(vv[e]); hf[e] = __half2float(hh[e]); }
    ((__half2*)h)[i * 2]     = __halves2half2(hh[0], hh[1]);
    ((__half2*)h)[i * 2 + 1] = __halves2half2(hh[2], hh[3]);
    ((uint16_t*)p5)[i * 2]     = f2_e5m2(vv[0] * 0.015625f, vv[1] * 0.015625f);
    ((uint16_t*)p5)[i * 2 + 1] = f2_e5m2(vv[2] * 0.015625f, vv[3] * 0.015625f);
    ((uint16_t*)p4)[i * 2]     = f2_e4m3((vv[0] - hf[0]) * 4096.f, (vv[1] - hf[1]) * 4096.f);
    ((uint16_t*)p4)[i * 2 + 1] = f2_e4m3((vv[2] - hf[2]) * 4096.f, (vv[3] - hf[3]) * 4096.f);
}

// ---------------------------------------------------------------------------
__global__ void __launch_bounds__(256)
combine_stats()
{
    const int i = blockIdx.x * 256 + threadIdx.x;
    float m = NEG_INF;
#pragma unroll 4
    for (int t = 0; t < NTILE; t++)
        m = fmaxf(m, g_cm[(size_t)t * BATCH * SEQ + i]);
    float zz = 0.f;
#pragma unroll 4
    for (int t = 0; t < NTILE; t++) {
        const size_t o = (size_t)t * BATCH * SEQ + i;
        zz += g_cz[o] * fast_exp(g_cm[o] - m);
    }
    g_m[i]  = m;
    g_rz[i] = 1.0f / zz;
}

// ---------------------------------------------------------------------------
// P = exp(S - m_k) * rz_k  -> single fp16 plane
__global__ void __launch_bounds__(256)
ppass()
{
    const int b = blockIdx.z;
    const size_t idx = ((size_t)blockIdx.x * 256 + threadIdx.x) * 4;
    const int k = (int)(idx & (SEQ - 1));

    const float4 s4 = *(const float4*)(g_S + (size_t)b * SEQ * SEQ + idx);
    const float4 m4 = *(const float4*)(g_m  + (size_t)b * SEQ + k);
    const float4 r4 = *(const float4*)(g_rz + (size_t)b * SEQ + k);

    __half h0 = __float2half_rn(fast_exp(s4.x - m4.x) * r4.x);
    __half h1 = __float2half_rn(fast_exp(s4.y - m4.y) * r4.y);
    __half h2 = __float2half_rn(fast_exp(s4.z - m4.z) * r4.z);
    __half h3 = __float2half_rn(fast_exp(s4.w - m4.w) * r4.w);

    const size_t o2 = ((size_t)b * SEQ * SEQ + idx) / 2;
    ((__half2*)g_Ph)[o2]     = __halves2half2(h0, h1);
    ((__half2*)g_Ph)[o2 + 1] = __halves2half2(h2, h3);
}

// ---------------------------------------------------------------------------
extern "C" void kernel_launch(void* const* d_in, const int* in_sizes, int n_in,
                              void* d_out, int out_size)
{
    const float* X  = (const float*)d_in[0];
    const float* Wq = (const float*)d_in[1];
    const float* bq = (const float*)d_in[2];
    const float* Wk = (const float*)d_in[3];
    const float* bk = (const float*)d_in[4];
    const float* Wv = (const float*)d_in[5];
    const float* bv = (const float*)d_in[6];
    float* out = (float*)d_out;

    __half  *pXh, *pWh, *pQh, *pKh, *pVth, *pPh;
    uint8_t *pX4, *pX5, *pW5, *pW4, *pQ4, *pQ5, *pK4, *pK5;
    float   *pS;
    cudaGetSymbolAddress((void**)&pXh,  g_Xh);
    cudaGetSymbolAddress((void**)&pX4,  g_X4);
    cudaGetSymbolAddress((void**)&pX5,  g_X5);
    cudaGetSymbolAddress((void**)&pWh,  g_Wh);
    cudaGetSymbolAddress((void**)&pW5,  g_W5);
    cudaGetSymbolAddress((void**)&pW4,  g_W4);
    cudaGetSymbolAddress((void**)&pQh,  g_Qh);
    cudaGetSymbolAddress((void**)&pQ4,  g_Q4);
    cudaGetSymbolAddress((void**)&pQ5,  g_Q5);
    cudaGetSymbolAddress((void**)&pKh,  g_Kh);
    cudaGetSymbolAddress((void**)&pK4,  g_K4);
    cudaGetSymbolAddress((void**)&pK5,  g_K5);
    cudaGetSymbolAddress((void**)&pVth, g_Vth);
    cudaGetSymbolAddress((void**)&pPh,  g_Ph);
    cudaGetSymbolAddress((void**)&pS,   g_S);

    cudaFuncSetAttribute((const void*)gemm_f8<1,1>, cudaFuncAttributeMaxDynamicSharedMemorySize, 65536);
    cudaFuncSetAttribute((const void*)gemm_f8<2,1>, cudaFuncAttributeMaxDynamicSharedMemorySize, 65536);
    cudaFuncSetAttribute((const void*)gemm_f8<3,1>, cudaFuncAttributeMaxDynamicSharedMemorySize, 65536);
    cudaFuncSetAttribute((const void*)gemm_f8<0,0>, cudaFuncAttributeMaxDynamicSharedMemorySize, 32768);

    const dim3 blk(TCT);
    const int WSZ = DIM * DIM;

    // input splits
    split_x<<<(MTOT * DIM / 4 + 255) / 256, 256>>>(X, pXh, pX4, pX5, MTOT * DIM / 4);
    split_w<<<(WSZ / 4 + 255) / 256, 256>>>(Wq, pWh,           pW5,           pW4,           WSZ / 4);
    split_w<<<(WSZ / 4 + 255) / 256, 256>>>(Wk, pWh + WSZ,     pW5 + WSZ,     pW4 + WSZ,     WSZ / 4);
    split_w<<<(WSZ / 4 + 255) / 256, 256>>>(Wv, pWh + 2 * WSZ, pW5 + 2 * WSZ, pW4 + 2 * WSZ, WSZ / 4);

    // QKV projections (K=512): fp16 hi*hi + fp8 corrections
    const dim3 gQKV(DIM / 128, MTOT / 128, 1);
    gemm_f8<1,1><<<gQKV, blk, 65536>>>(pXh, pX4, pX5, pWh,           pW5,           pW4,           bq,
                                       nullptr, pQh, pQ4, pQ5, DIM, DIM, DIM, DIM, 0, 0, 0);
    gemm_f8<1,1><<<gQKV, blk, 65536>>>(pXh, pX4, pX5, pWh + WSZ,     pW5 + WSZ,     pW4 + WSZ,     bk,
                                       nullptr, pKh, pK4, pK5, DIM, DIM, DIM, DIM, 0, 0, 0);
    gemm_f8<2,1><<<gQKV, blk, 65536>>>(pXh, pX4, pX5, pWh + 2 * WSZ, pW5 + 2 * WSZ, pW4 + 2 * WSZ, bv,
                                       nullptr, pVth, nullptr, nullptr, DIM, DIM, DIM, MTOT, 0, 0, 0);

    // S = Q K^T per batch (K=512), fp32 out + fused column stats partials
    const dim3 gS(SEQ / 128, SEQ / 128, BATCH);
    gemm_f8<3,1><<<gS, blk, 65536>>>(pQh, pQ4, pQ5, pKh, pK5, pK4, nullptr,
                                     pS, nullptr, nullptr, nullptr, DIM, DIM, DIM, SEQ,
                                     (long)SEQ * DIM, (long)SEQ * DIM, (long)SEQ * SEQ);

    // merge partial stats
    combine_stats<<<(BATCH * SEQ) / 256, 256>>>();

    // P = exp(S - m) * rz -> single fp16 plane
    ppass<<<dim3((SEQ * SEQ) / (256 * 4), 1, BATCH), blk>>>();

    // O = P V per batch (K=4096), single fp16 MMA path
    const dim3 gPV(DIM / 128, SEQ / 128, BATCH);
    gemm_f8<0,0><<<gPV, blk, 32768>>>(pPh, nullptr, nullptr, pVth, nullptr, nullptr, nullptr,
                                      out, nullptr, nullptr, nullptr, SEQ, SEQ, MTOT, DIM,
                                      (long)SEQ * SEQ, SEQ, (long)SEQ * DIM);
}